// round 14
// baseline (speedup 1.0000x reference)
#include <cuda_runtime.h>

#define C_ATOM 128
#define C_REF  389
#define C_PAIR 16
#define CL_ROWS 8          // rows per cl block (8 warps x 1 row)
#define PLM_ITERS 4        // 64 pairs/iter * 4 = 256 pairs/block

// ---------------------------------------------------------------------------
// Fused kernel (R13 skeleton; single change: plm stores use DEFAULT write-back
// policy instead of .cs streaming, letting the 126MB L2 absorb and schedule
// HBM writebacks with deeper bank parallelism).
//
// Blocks [0, clBlocks):  cl = feats @ W_feats + b_feats (8 warps x 1 row).
//   cl blocks MUST be first: in wave 0 their L2 latency hides under plm
//   warps; any late cl block adds its bare ~15us to the makespan (R10/R11).
// Blocks [clBlocks, ..): plm, 256 pairs/block, 4 threads/pair.
//   Phase A: 4 independent uid LDGs + 4 UNCONDITIONAL zero STG.128
//            (dependency-free store stream at memset-like issue rate).
//   Phase B: rare (~0.4%) matching slots recomputed and re-stored by the
//            same thread (program order to same address -> nonzero wins).
// ---------------------------------------------------------------------------
__global__ void __launch_bounds__(256, 8)
fused_kernel(const float* __restrict__ pos,
             const float* __restrict__ charge,
             const float* __restrict__ mask,
             const float* __restrict__ elem,
             const float* __restrict__ names,
             const int*   __restrict__ uid,
             const float* __restrict__ Wf,
             const float* __restrict__ bf,
             const float* __restrict__ Woff,
             const float* __restrict__ boff,
             const float* __restrict__ Winv,
             const float* __restrict__ binv,
             const float* __restrict__ Wvm,
             const float* __restrict__ bvm,
             float* __restrict__ out, int N, int clBlocks)
{
    __shared__ float sf[CL_ROWS][C_REF];

    const int tid = threadIdx.x;

    if (blockIdx.x < (unsigned)clBlocks) {
        // ------------------------- cl path ---------------------------------
        const int n0   = blockIdx.x * CL_ROWS;
        const int warp = tid >> 5;
        const int lane = tid & 31;

        for (int idx = tid; idx < CL_ROWS * C_REF; idx += 256) {
            int r = idx / C_REF;
            int j = idx - r * C_REF;
            int n = n0 + r;
            float v;
            if (j < 3)        v = pos[n * 3 + j];
            else if (j == 3)  v = charge[n];
            else if (j == 4)  v = mask[n];
            else if (j < 133) v = elem[n * 128 + (j - 5)];
            else              v = names[n * 256 + (j - 133)];
            sf[r][j] = v;
        }
        __syncthreads();

        const int c4 = lane * 4;
        float4 acc = *reinterpret_cast<const float4*>(bf + c4);

#pragma unroll 4
        for (int j = 0; j < C_REF; j++) {
            float4 w = *reinterpret_cast<const float4*>(Wf + j * C_ATOM + c4);
            float  f = sf[warp][j];
            acc.x = fmaf(w.x, f, acc.x);
            acc.y = fmaf(w.y, f, acc.y);
            acc.z = fmaf(w.z, f, acc.z);
            acc.w = fmaf(w.w, f, acc.w);
        }
        *reinterpret_cast<float4*>(out + (long long)(n0 + warp) * C_ATOM + c4) = acc;
        return;
    }

    // --------------------------- plm path ----------------------------------
    const int pair = tid >> 2;           // 0..63
    const int kg   = (tid & 3) * 4;      // 0,4,8,12

    const long long pbase = (long long)(blockIdx.x - clBlocks) * (64 * PLM_ITERS);
    const int l  = (int)(pbase / N);
    const int m0 = (int)(pbase - (long long)l * N) + pair;

    const int ul = __ldg(uid + l);

    float* op = out + (long long)N * C_ATOM + (pbase + pair) * C_PAIR + kg;

    // Phase A: batch all uid loads (independent) ...
    int um[PLM_ITERS];
#pragma unroll
    for (int it = 0; it < PLM_ITERS; it++)
        um[it] = __ldg(uid + m0 + it * 64);

    // ... and all zero stores (no dependencies; default write-back policy).
    const float4 z = make_float4(0.f, 0.f, 0.f, 0.f);
#pragma unroll
    for (int it = 0; it < PLM_ITERS; it++)
        *reinterpret_cast<float4*>(op + (long long)it * (64 * C_PAIR)) = z;

    // Phase B: rare overwrites (same thread, same address -> ordered).
#pragma unroll
    for (int it = 0; it < PLM_ITERS; it++) {
        if (um[it] == ul) {
            const int m = m0 + it * 64;
            const float d0 = __ldg(pos + l * 3 + 0) - __ldg(pos + m * 3 + 0);
            const float d1 = __ldg(pos + l * 3 + 1) - __ldg(pos + m * 3 + 1);
            const float d2 = __ldg(pos + l * 3 + 2) - __ldg(pos + m * 3 + 2);
            float s = fmaf(d0, d0, 1.0f);
            s = fmaf(d1, d1, s);
            s = fmaf(d2, d2, s);
            const float inv = __fdividef(1.0f, s);

            float4 r;
#pragma unroll
            for (int q = 0; q < 4; q++) {
                const int c = kg + q;
                float t = __ldg(boff + c) + __ldg(binv + c)
                        + __ldg(Wvm + c) + __ldg(bvm + c);
                t = fmaf(d0,  __ldg(Woff + c),              t);
                t = fmaf(d1,  __ldg(Woff + C_PAIR + c),     t);
                t = fmaf(d2,  __ldg(Woff + 2 * C_PAIR + c), t);
                t = fmaf(inv, __ldg(Winv + c),              t);
                (&r.x)[q] = t;
            }
            *reinterpret_cast<float4*>(op + (long long)it * (64 * C_PAIR)) = r;
        }
    }
}

// ---------------------------------------------------------------------------
// Launch: single kernel; 256 cl blocks FIRST (wave 0), then 16384 plm blocks.
// ---------------------------------------------------------------------------
extern "C" void kernel_launch(void* const* d_in, const int* in_sizes, int n_in,
                              void* d_out, int out_size)
{
    const float* pos    = (const float*)d_in[0];
    const float* charge = (const float*)d_in[1];
    const float* maskp  = (const float*)d_in[2];
    const float* elem   = (const float*)d_in[3];
    const float* names  = (const float*)d_in[4];
    const int*   uid    = (const int*)  d_in[5];
    const float* Wf     = (const float*)d_in[6];
    const float* bf     = (const float*)d_in[7];
    const float* Woff   = (const float*)d_in[8];
    const float* boff   = (const float*)d_in[9];
    const float* Winv   = (const float*)d_in[10];
    const float* binv   = (const float*)d_in[11];
    const float* Wvm    = (const float*)d_in[12];
    const float* bvm    = (const float*)d_in[13];

    const int N = in_sizes[1];  // B*N with B=1
    float* out = (float*)d_out;

    const int clBlocks = N / CL_ROWS;                           // 256
    const long long pairs = (long long)N * N;
    const int plmBlocks = (int)(pairs / (64 * PLM_ITERS));      // 16384

    fused_kernel<<<clBlocks + plmBlocks, 256>>>(
        pos, charge, maskp, elem, names, uid, Wf, bf,
        Woff, boff, Winv, binv, Wvm, bvm, out, N, clBlocks);
}

// round 15
// speedup vs baseline: 1.4901x; 1.4901x over previous
#include <cuda_runtime.h>

#define C_ATOM 128
#define C_REF  389
#define C_PAIR 16
#define CL_ROWS 8          // rows per cl block (8 warps x 1 row)
#define PLM_ITERS 4        // 64 pairs/iter * 4 = 256 pairs/block

// ---------------------------------------------------------------------------
// FINAL kernel (R13 configuration — best measured: 55.36us, ~97% of the
// demonstrated HBM write ceiling for this buffer).
//
// Design facts established by controlled experiments (R1-R14):
//  * plm output is 268MB, ~99.6% exact zeros (uid match rate ~1/256):
//    zero path = LDG uid + dependency-free STG.cs.128 stream.
//  * .cs streaming stores are mandatory (write-back L2 thrash: +27us).
//  * STG.128 via 4 threads/pair is the optimal store shape (v8: 2x worse).
//  * cl blocks must occupy wave 0 (latency hidden under plm warps; any
//    late cl block adds its bare ~15us to the makespan).
//  * Batched phase split (all loads, then all stores, then rare overwrites)
//    decouples store issue from the load scoreboard.
// ---------------------------------------------------------------------------
__global__ void __launch_bounds__(256, 8)
fused_kernel(const float* __restrict__ pos,
             const float* __restrict__ charge,
             const float* __restrict__ mask,
             const float* __restrict__ elem,
             const float* __restrict__ names,
             const int*   __restrict__ uid,
             const float* __restrict__ Wf,
             const float* __restrict__ bf,
             const float* __restrict__ Woff,
             const float* __restrict__ boff,
             const float* __restrict__ Winv,
             const float* __restrict__ binv,
             const float* __restrict__ Wvm,
             const float* __restrict__ bvm,
             float* __restrict__ out, int N, int clBlocks)
{
    __shared__ float sf[CL_ROWS][C_REF];

    const int tid = threadIdx.x;

    if (blockIdx.x < (unsigned)clBlocks) {
        // ------------------------- cl path ---------------------------------
        const int n0   = blockIdx.x * CL_ROWS;
        const int warp = tid >> 5;
        const int lane = tid & 31;

        for (int idx = tid; idx < CL_ROWS * C_REF; idx += 256) {
            int r = idx / C_REF;
            int j = idx - r * C_REF;
            int n = n0 + r;
            float v;
            if (j < 3)        v = pos[n * 3 + j];
            else if (j == 3)  v = charge[n];
            else if (j == 4)  v = mask[n];
            else if (j < 133) v = elem[n * 128 + (j - 5)];
            else              v = names[n * 256 + (j - 133)];
            sf[r][j] = v;
        }
        __syncthreads();

        const int c4 = lane * 4;
        float4 acc = *reinterpret_cast<const float4*>(bf + c4);

#pragma unroll 4
        for (int j = 0; j < C_REF; j++) {
            float4 w = *reinterpret_cast<const float4*>(Wf + j * C_ATOM + c4);
            float  f = sf[warp][j];
            acc.x = fmaf(w.x, f, acc.x);
            acc.y = fmaf(w.y, f, acc.y);
            acc.z = fmaf(w.z, f, acc.z);
            acc.w = fmaf(w.w, f, acc.w);
        }
        *reinterpret_cast<float4*>(out + (long long)(n0 + warp) * C_ATOM + c4) = acc;
        return;
    }

    // --------------------------- plm path ----------------------------------
    const int pair = tid >> 2;           // 0..63
    const int kg   = (tid & 3) * 4;      // 0,4,8,12

    const long long pbase = (long long)(blockIdx.x - clBlocks) * (64 * PLM_ITERS);
    const int l  = (int)(pbase / N);
    const int m0 = (int)(pbase - (long long)l * N) + pair;

    const int ul = __ldg(uid + l);

    float* op = out + (long long)N * C_ATOM + (pbase + pair) * C_PAIR + kg;

    // Phase A: batch all uid loads (independent) ...
    int um[PLM_ITERS];
#pragma unroll
    for (int it = 0; it < PLM_ITERS; it++)
        um[it] = __ldg(uid + m0 + it * 64);

    // ... and all zero stores (no dependencies: pure store-issue stream).
    const float4 z = make_float4(0.f, 0.f, 0.f, 0.f);
#pragma unroll
    for (int it = 0; it < PLM_ITERS; it++)
        __stcs(reinterpret_cast<float4*>(op + (long long)it * (64 * C_PAIR)), z);

    // Phase B: rare overwrites (same thread, same address -> ordered).
#pragma unroll
    for (int it = 0; it < PLM_ITERS; it++) {
        if (um[it] == ul) {
            const int m = m0 + it * 64;
            const float d0 = __ldg(pos + l * 3 + 0) - __ldg(pos + m * 3 + 0);
            const float d1 = __ldg(pos + l * 3 + 1) - __ldg(pos + m * 3 + 1);
            const float d2 = __ldg(pos + l * 3 + 2) - __ldg(pos + m * 3 + 2);
            float s = fmaf(d0, d0, 1.0f);
            s = fmaf(d1, d1, s);
            s = fmaf(d2, d2, s);
            const float inv = __fdividef(1.0f, s);

            float4 r;
#pragma unroll
            for (int q = 0; q < 4; q++) {
                const int c = kg + q;
                float t = __ldg(boff + c) + __ldg(binv + c)
                        + __ldg(Wvm + c) + __ldg(bvm + c);
                t = fmaf(d0,  __ldg(Woff + c),              t);
                t = fmaf(d1,  __ldg(Woff + C_PAIR + c),     t);
                t = fmaf(d2,  __ldg(Woff + 2 * C_PAIR + c), t);
                t = fmaf(inv, __ldg(Winv + c),              t);
                (&r.x)[q] = t;
            }
            __stcs(reinterpret_cast<float4*>(op + (long long)it * (64 * C_PAIR)), r);
        }
    }
}

// ---------------------------------------------------------------------------
// Launch: single kernel; 256 cl blocks FIRST (wave 0), then 16384 plm blocks.
// ---------------------------------------------------------------------------
extern "C" void kernel_launch(void* const* d_in, const int* in_sizes, int n_in,
                              void* d_out, int out_size)
{
    const float* pos    = (const float*)d_in[0];
    const float* charge = (const float*)d_in[1];
    const float* maskp  = (const float*)d_in[2];
    const float* elem   = (const float*)d_in[3];
    const float* names  = (const float*)d_in[4];
    const int*   uid    = (const int*)  d_in[5];
    const float* Wf     = (const float*)d_in[6];
    const float* bf     = (const float*)d_in[7];
    const float* Woff   = (const float*)d_in[8];
    const float* boff   = (const float*)d_in[9];
    const float* Winv   = (const float*)d_in[10];
    const float* binv   = (const float*)d_in[11];
    const float* Wvm    = (const float*)d_in[12];
    const float* bvm    = (const float*)d_in[13];

    const int N = in_sizes[1];  // B*N with B=1
    float* out = (float*)d_out;

    const int clBlocks = N / CL_ROWS;                           // 256
    const long long pairs = (long long)N * N;
    const int plmBlocks = (int)(pairs / (64 * PLM_ITERS));      // 16384

    fused_kernel<<<clBlocks + plmBlocks, 256>>>(
        pos, charge, maskp, elem, names, uid, Wf, bf,
        Woff, boff, Winv, binv, Wvm, bvm, out, N, clBlocks);
}

// round 16
// speedup vs baseline: 1.5838x; 1.0629x over previous
#include <cuda_runtime.h>

#define C_ATOM 128
#define C_REF  389
#define C_PAIR 16
#define CL_ROWS 16         // rows per cl block (16 warps x 1 row, 512 thr)
#define PLM_ITERS 4        // 128 pairs/iter * 4 = 512 pairs/block

// ---------------------------------------------------------------------------
// Final-family kernel: identical per-warp structure to the 55.2us winner,
// but 512-thread blocks at 4 blocks/SM (same 64 warps/SM) — halves block
// count and block-boundary effects in the store stream.
//
// Blocks [0, clBlocks):  cl = feats @ W_feats + b_feats (16 warps x 1 row).
//   cl blocks MUST be first (wave 0): latency hides under plm warps.
// Blocks [clBlocks, ..): plm, 512 pairs/block, 4 threads/pair.
//   Phase A: 4 independent uid LDGs + 4 UNCONDITIONAL zero STG.cs.128.
//   Phase B: rare (~0.4%) matching slots recomputed and re-stored by the
//            same thread (program order to same address -> nonzero wins).
// ---------------------------------------------------------------------------
__global__ void __launch_bounds__(512, 4)
fused_kernel(const float* __restrict__ pos,
             const float* __restrict__ charge,
             const float* __restrict__ mask,
             const float* __restrict__ elem,
             const float* __restrict__ names,
             const int*   __restrict__ uid,
             const float* __restrict__ Wf,
             const float* __restrict__ bf,
             const float* __restrict__ Woff,
             const float* __restrict__ boff,
             const float* __restrict__ Winv,
             const float* __restrict__ binv,
             const float* __restrict__ Wvm,
             const float* __restrict__ bvm,
             float* __restrict__ out, int N, int clBlocks)
{
    __shared__ float sf[CL_ROWS][C_REF];

    const int tid = threadIdx.x;

    if (blockIdx.x < (unsigned)clBlocks) {
        // ------------------------- cl path ---------------------------------
        const int n0   = blockIdx.x * CL_ROWS;
        const int warp = tid >> 5;
        const int lane = tid & 31;

        for (int idx = tid; idx < CL_ROWS * C_REF; idx += 512) {
            int r = idx / C_REF;
            int j = idx - r * C_REF;
            int n = n0 + r;
            float v;
            if (j < 3)        v = pos[n * 3 + j];
            else if (j == 3)  v = charge[n];
            else if (j == 4)  v = mask[n];
            else if (j < 133) v = elem[n * 128 + (j - 5)];
            else              v = names[n * 256 + (j - 133)];
            sf[r][j] = v;
        }
        __syncthreads();

        const int c4 = lane * 4;
        float4 acc = *reinterpret_cast<const float4*>(bf + c4);

#pragma unroll 4
        for (int j = 0; j < C_REF; j++) {
            float4 w = *reinterpret_cast<const float4*>(Wf + j * C_ATOM + c4);
            float  f = sf[warp][j];
            acc.x = fmaf(w.x, f, acc.x);
            acc.y = fmaf(w.y, f, acc.y);
            acc.z = fmaf(w.z, f, acc.z);
            acc.w = fmaf(w.w, f, acc.w);
        }
        *reinterpret_cast<float4*>(out + (long long)(n0 + warp) * C_ATOM + c4) = acc;
        return;
    }

    // --------------------------- plm path ----------------------------------
    const int pair = tid >> 2;           // 0..127
    const int kg   = (tid & 3) * 4;      // 0,4,8,12

    const long long pbase = (long long)(blockIdx.x - clBlocks) * (128 * PLM_ITERS);
    const int l  = (int)(pbase / N);
    const int m0 = (int)(pbase - (long long)l * N) + pair;

    const int ul = __ldg(uid + l);

    float* op = out + (long long)N * C_ATOM + (pbase + pair) * C_PAIR + kg;

    // Phase A: batch all uid loads (independent) ...
    int um[PLM_ITERS];
#pragma unroll
    for (int it = 0; it < PLM_ITERS; it++)
        um[it] = __ldg(uid + m0 + it * 128);

    // ... and all zero stores (no dependencies: pure store-issue stream).
    const float4 z = make_float4(0.f, 0.f, 0.f, 0.f);
#pragma unroll
    for (int it = 0; it < PLM_ITERS; it++)
        __stcs(reinterpret_cast<float4*>(op + (long long)it * (128 * C_PAIR)), z);

    // Phase B: rare overwrites (same thread, same address -> ordered).
#pragma unroll
    for (int it = 0; it < PLM_ITERS; it++) {
        if (um[it] == ul) {
            const int m = m0 + it * 128;
            const float d0 = __ldg(pos + l * 3 + 0) - __ldg(pos + m * 3 + 0);
            const float d1 = __ldg(pos + l * 3 + 1) - __ldg(pos + m * 3 + 1);
            const float d2 = __ldg(pos + l * 3 + 2) - __ldg(pos + m * 3 + 2);
            float s = fmaf(d0, d0, 1.0f);
            s = fmaf(d1, d1, s);
            s = fmaf(d2, d2, s);
            const float inv = __fdividef(1.0f, s);

            float4 r;
#pragma unroll
            for (int q = 0; q < 4; q++) {
                const int c = kg + q;
                float t = __ldg(boff + c) + __ldg(binv + c)
                        + __ldg(Wvm + c) + __ldg(bvm + c);
                t = fmaf(d0,  __ldg(Woff + c),              t);
                t = fmaf(d1,  __ldg(Woff + C_PAIR + c),     t);
                t = fmaf(d2,  __ldg(Woff + 2 * C_PAIR + c), t);
                t = fmaf(inv, __ldg(Winv + c),              t);
                (&r.x)[q] = t;
            }
            __stcs(reinterpret_cast<float4*>(op + (long long)it * (128 * C_PAIR)), r);
        }
    }
}

// ---------------------------------------------------------------------------
// Launch: single kernel; 128 cl blocks FIRST (wave 0), then 8192 plm blocks.
// ---------------------------------------------------------------------------
extern "C" void kernel_launch(void* const* d_in, const int* in_sizes, int n_in,
                              void* d_out, int out_size)
{
    const float* pos    = (const float*)d_in[0];
    const float* charge = (const float*)d_in[1];
    const float* maskp  = (const float*)d_in[2];
    const float* elem   = (const float*)d_in[3];
    const float* names  = (const float*)d_in[4];
    const int*   uid    = (const int*)  d_in[5];
    const float* Wf     = (const float*)d_in[6];
    const float* bf     = (const float*)d_in[7];
    const float* Woff   = (const float*)d_in[8];
    const float* boff   = (const float*)d_in[9];
    const float* Winv   = (const float*)d_in[10];
    const float* binv   = (const float*)d_in[11];
    const float* Wvm    = (const float*)d_in[12];
    const float* bvm    = (const float*)d_in[13];

    const int N = in_sizes[1];  // B*N with B=1
    float* out = (float*)d_out;

    const int clBlocks = N / CL_ROWS;                           // 128
    const long long pairs = (long long)N * N;
    const int plmBlocks = (int)(pairs / (128 * PLM_ITERS));     // 8192

    fused_kernel<<<clBlocks + plmBlocks, 512>>>(
        pos, charge, maskp, elem, names, uid, Wf, bf,
        Woff, boff, Winv, binv, Wvm, bvm, out, N, clBlocks);
}